// round 14
// baseline (speedup 1.0000x reference)
#include <cuda_runtime.h>
#include <cuda_bf16.h>
#include <cstdint>
#include <cstddef>

#define BB 2
#define SS 2048
#define DD 1024
#define HH 16
#define DHH 64
#define WINDOW 256
#define MM (BB * SS)        // 4096 activation rows
#define ROWB 4096           // bytes per operand row: [bf16hi 2048 | i8a 1024 | i8b 1024]
#define NSTG 64             // 16 (Al*Wh i8) + 16 (Ah*Wl i8) + 32 (bf16 hi*hi)

// quantization scales: S_a=6, S_w=0.2, residual scales S/384
#define INV_A  (127.0f / 6.0f)
#define INV_AL (127.0f * 384.0f / 6.0f)
#define INV_W  (127.0f / 0.2f)
#define INV_WL (127.0f * 384.0f / 0.2f)
#define KAPPA  ((6.0f / 127.0f) * (0.2f / (127.0f * 384.0f)))

// ---------------- scratch (__device__ globals; no allocs allowed) ----------
__device__ __nv_bfloat16 g_qh[(size_t)MM * DD];   // projected Q hi (pre-scaled 0.125)
__device__ __nv_bfloat16 g_ql[(size_t)MM * DD];
__device__ __nv_bfloat16 g_kh[(size_t)MM * DD];
__device__ __nv_bfloat16 g_kl[(size_t)MM * DD];
__device__ __nv_bfloat16 g_vh[(size_t)MM * DD];
__device__ __nv_bfloat16 g_vl[(size_t)MM * DD];
// A operands: per row [ahi bf16 x1024 | al_i8 x1024 | a_i8 x1024]
__device__ char g_a2q[(size_t)MM * ROWB];
__device__ char g_a2k[(size_t)MM * ROWB];
__device__ char g_a2v[(size_t)MM * ROWB];
__device__ char g_a2o[(size_t)MM * ROWB];
// W operands: per row [whi bf16 x1024 | w_i8 x1024 | wl_i8 x1024]
__device__ char g_w2q[(size_t)DD * ROWB];
__device__ char g_w2k[(size_t)DD * ROWB];
__device__ char g_w2v[(size_t)DD * ROWB];
__device__ char g_w2o[(size_t)DD * ROWB];

// ---------------- PTX helpers ----------------------------------------------
__device__ __forceinline__ uint32_t smem_u32(const void* p) {
    uint32_t a;
    asm("{ .reg .u64 t; cvta.to.shared.u64 t, %1; cvt.u32.u64 %0, t; }"
        : "=r"(a) : "l"(p));
    return a;
}
__device__ __forceinline__ void cp_async16(uint32_t saddr, const void* gaddr) {
    asm volatile("cp.async.cg.shared.global [%0], [%1], 16;"
                 :: "r"(saddr), "l"(gaddr));
}
#define CP_COMMIT() asm volatile("cp.async.commit_group;" ::: "memory")
#define CP_WAIT2()  asm volatile("cp.async.wait_group 2;" ::: "memory")
#define CP_WAIT0()  asm volatile("cp.async.wait_group 0;" ::: "memory")

__device__ __forceinline__ void ldmatrix_x4(uint32_t* r, uint32_t addr) {
    asm volatile("ldmatrix.sync.aligned.m8n8.x4.shared.b16 {%0,%1,%2,%3}, [%4];"
                 : "=r"(r[0]), "=r"(r[1]), "=r"(r[2]), "=r"(r[3]) : "r"(addr));
}
__device__ __forceinline__ void ldmatrix_x4_trans(uint32_t* r, uint32_t addr) {
    asm volatile("ldmatrix.sync.aligned.m8n8.x4.trans.shared.b16 {%0,%1,%2,%3}, [%4];"
                 : "=r"(r[0]), "=r"(r[1]), "=r"(r[2]), "=r"(r[3]) : "r"(addr));
}
__device__ __forceinline__ void mma_bf16(float* d, const uint32_t* a,
                                         uint32_t b0, uint32_t b1) {
    asm volatile(
        "mma.sync.aligned.m16n8k16.row.col.f32.bf16.bf16.f32 "
        "{%0,%1,%2,%3}, {%4,%5,%6,%7}, {%8,%9}, {%0,%1,%2,%3};"
        : "+f"(d[0]), "+f"(d[1]), "+f"(d[2]), "+f"(d[3])
        : "r"(a[0]), "r"(a[1]), "r"(a[2]), "r"(a[3]), "r"(b0), "r"(b1));
}
__device__ __forceinline__ void mma_s8(int* d, const uint32_t* a,
                                       uint32_t b0, uint32_t b1) {
    asm volatile(
        "mma.sync.aligned.m16n8k32.row.col.s32.s8.s8.s32 "
        "{%0,%1,%2,%3}, {%4,%5,%6,%7}, {%8,%9}, {%0,%1,%2,%3};"
        : "+r"(d[0]), "+r"(d[1]), "+r"(d[2]), "+r"(d[3])
        : "r"(a[0]), "r"(a[1]), "r"(a[2]), "r"(a[3]), "r"(b0), "r"(b1));
}
__device__ __forceinline__ uint32_t pack_bf16x2(float a, float b) {
    __nv_bfloat162 t;
    t.x = __float2bfloat16(a);
    t.y = __float2bfloat16(b);
    return *(uint32_t*)&t;
}
__device__ __forceinline__ int sat8(float x, float inv) {
    int i = __float2int_rn(x * inv);
    return max(-127, min(127, i));
}
__device__ __forceinline__ uint32_t pack4i8(int a, int b, int c, int d) {
    return (uint32_t)(a & 255) | ((uint32_t)(b & 255) << 8) |
           ((uint32_t)(c & 255) << 16) | ((uint32_t)(d & 255) << 24);
}

// per-stage byte offset within an operand row:
//   s 0..15  -> 2048 + s*64        (A: al_i8   | W: w_i8)
//   s 16..31 -> 3072 + (s-16)*64   (A: a_i8    | W: wl_i8)
//   s 32..63 -> (s-32)*64          (bf16 hi block)
__device__ __forceinline__ uint32_t stage_off(int s) {
    return (s < 32) ? (2048u + ((uint32_t)(s >> 4) << 10) + ((uint32_t)(s & 15) << 6))
                    : ((uint32_t)(s - 32) << 6);
}

// ---------------------------------------------------------------------------
// Fused prep: all 7 operand conversions in one launch.
// grid (4096, 7): y=0..3 -> Wq/Wk/Wv/Wo ; y=4..6 -> query/key/value.
// ---------------------------------------------------------------------------
__global__ void prep_kernel(const float* __restrict__ query,
                            const float* __restrict__ key,
                            const float* __restrict__ value,
                            const float* __restrict__ Wq,
                            const float* __restrict__ Wk,
                            const float* __restrict__ Wv,
                            const float* __restrict__ Wo)
{
    const int y = blockIdx.y;
    const int row = blockIdx.x;
    const float* in;
    char* out;
    bool amode;
    if (y < 4) {
        if (row >= DD) return;
        amode = false;
        in  = (y == 0) ? Wq : (y == 1) ? Wk : (y == 2) ? Wv : Wo;
        out = (y == 0) ? g_w2q : (y == 1) ? g_w2k : (y == 2) ? g_w2v : g_w2o;
    } else {
        amode = true;
        in  = (y == 4) ? query : (y == 5) ? key : value;
        out = (y == 4) ? g_a2q : (y == 5) ? g_a2k : g_a2v;
    }
    const int c4 = threadIdx.x;            // 0..255, covers cols 4c4..4c4+3
    float4 f = ((const float4*)in)[(size_t)row * 256 + c4];

    __nv_bfloat16 h0 = __float2bfloat16(f.x);
    __nv_bfloat16 h1 = __float2bfloat16(f.y);
    __nv_bfloat16 h2 = __float2bfloat16(f.z);
    __nv_bfloat16 h3 = __float2bfloat16(f.w);
    float r0 = f.x - __bfloat162float(h0);
    float r1 = f.y - __bfloat162float(h1);
    float r2 = f.z - __bfloat162float(h2);
    float r3 = f.w - __bfloat162float(h3);

    __nv_bfloat162 hp0, hp1;
    hp0.x = h0; hp0.y = h1; hp1.x = h2; hp1.y = h3;

    char* rb = out + (size_t)row * ROWB;
    ((uint32_t*)(rb + c4 * 8))[0] = *(uint32_t*)&hp0;
    ((uint32_t*)(rb + c4 * 8))[1] = *(uint32_t*)&hp1;

    uint32_t ia, ib;
    if (amode) {
        // region1: al_i8 (residual), region2: a_i8 (full)
        ia = pack4i8(sat8(r0, INV_AL), sat8(r1, INV_AL),
                     sat8(r2, INV_AL), sat8(r3, INV_AL));
        ib = pack4i8(sat8(f.x, INV_A), sat8(f.y, INV_A),
                     sat8(f.z, INV_A), sat8(f.w, INV_A));
    } else {
        // region1: w_i8 (full), region2: wl_i8 (residual)
        ia = pack4i8(sat8(f.x, INV_W), sat8(f.y, INV_W),
                     sat8(f.z, INV_W), sat8(f.w, INV_W));
        ib = pack4i8(sat8(r0, INV_WL), sat8(r1, INV_WL),
                     sat8(r2, INV_WL), sat8(r3, INV_WL));
    }
    *(uint32_t*)(rb + 2048 + c4 * 4) = ia;
    *(uint32_t*)(rb + 3072 + c4 * 4) = ib;
}

// ---------------------------------------------------------------------------
// GEMM: C = A @ W^T + bias.  CTA 128x128, 8 warps (2Mx4N), warp tile 64x32.
// Stages 0..31: int8 k32 corrections (shared s32 accum, equal scales);
// stages 32..63: bf16 k16 hi*hi. Fold d = kappa*di between phases.
// ---------------------------------------------------------------------------
template <int OSPLIT>
__device__ __forceinline__ void gemm_body(
    const char* __restrict__ A2, const char* __restrict__ W2,
    const float* __restrict__ bias, float* __restrict__ C,
    __nv_bfloat16* __restrict__ Chi, __nv_bfloat16* __restrict__ Clo,
    float oscale, char* smem_raw)
{
    const uint32_t smem = smem_u32(smem_raw);

    const int tid  = threadIdx.x;          // 0..255
    const int wid  = tid >> 5;
    const int lane = tid & 31;
    const int wm = wid & 1;
    const int wn = wid >> 1;               // 0..3
    const int n0 = blockIdx.x * 128;
    const int m0 = blockIdx.y * 128;

    const char* Abase = A2 + (size_t)m0 * ROWB;
    const char* Wbase = W2 + (size_t)n0 * ROWB;

    // cp.async: 1024 16B chunks/stage (A 512 + B 512), 4 per thread
    int lr[2], lc[2];
    uint32_t so[2];
#pragma unroll
    for (int i = 0; i < 2; i++) {
        int cl = tid + i * 256;
        lr[i] = cl >> 2;                   // 0..127
        lc[i] = cl & 3;
        so[i] = lr[i] * 64 + ((lc[i] ^ ((lr[i] >> 1) & 3)) << 4);
    }

    const int lane15 = lane & 15;
    const int hib = lane >> 4;
    uint32_t a_off[4], b_off[2];
    int a_sw[4], b_sw[2];
#pragma unroll
    for (int mt = 0; mt < 4; mt++) {
        int r = wm * 64 + mt * 16 + lane15;
        a_off[mt] = r * 64;
        a_sw[mt] = (r >> 1) & 3;
    }
#pragma unroll
    for (int bp = 0; bp < 2; bp++) {
        int r = wn * 32 + bp * 16 + lane15;
        b_off[bp] = 8192 + r * 64;
        b_sw[bp] = (r >> 1) & 3;
    }

    // prologue: prefetch stages 0..2
#pragma unroll
    for (int st = 0; st < 3; st++) {
        uint32_t sb = smem + (st & 3) * 16384;
        uint32_t off = stage_off(st);
#pragma unroll
        for (int i = 0; i < 2; i++) {
            cp_async16(sb + so[i],        Abase + (size_t)lr[i] * ROWB + off + lc[i] * 16);
            cp_async16(sb + 8192 + so[i], Wbase + (size_t)lr[i] * ROWB + off + lc[i] * 16);
        }
        CP_COMMIT();
    }

    float d[4][4][4];
    {
        int di[4][4][4];
#pragma unroll
        for (int mt = 0; mt < 4; mt++)
#pragma unroll
            for (int nt = 0; nt < 4; nt++)
#pragma unroll
                for (int x = 0; x < 4; x++) di[mt][nt][x] = 0;

        // ---- int8 phase: stages 0..31 ----
        for (int st = 0; st < 32; st++) {
            CP_WAIT2();
            __syncthreads();
            {
                uint32_t sb = smem + ((st + 3) & 3) * 16384;
                uint32_t off = stage_off(st + 3);
#pragma unroll
                for (int i = 0; i < 2; i++) {
                    cp_async16(sb + so[i],        Abase + (size_t)lr[i] * ROWB + off + lc[i] * 16);
                    cp_async16(sb + 8192 + so[i], Wbase + (size_t)lr[i] * ROWB + off + lc[i] * 16);
                }
            }
            CP_COMMIT();

            uint32_t base = smem + (st & 3) * 16384;
#pragma unroll
            for (int q = 0; q < 2; q++) {      // two k32 mmas per 64B stage
                int ch = q * 2 + hib;
                uint32_t a[4][4], bb[2][4];
#pragma unroll
                for (int mt = 0; mt < 4; mt++)
                    ldmatrix_x4(a[mt], base + a_off[mt] + ((ch ^ a_sw[mt]) << 4));
#pragma unroll
                for (int bp = 0; bp < 2; bp++)
                    ldmatrix_x4(bb[bp], base + b_off[bp] + ((ch ^ b_sw[bp]) << 4));
#pragma unroll
                for (int mt = 0; mt < 4; mt++)
#pragma unroll
                    for (int nt = 0; nt < 4; nt++)
                        mma_s8(di[mt][nt], a[mt],
                               bb[nt >> 1][nt & 1],
                               bb[nt >> 1][(nt & 1) + 2]);
            }
        }

        // fold int8 corrections into fp32 accumulators
#pragma unroll
        for (int mt = 0; mt < 4; mt++)
#pragma unroll
            for (int nt = 0; nt < 4; nt++)
#pragma unroll
                for (int x = 0; x < 4; x++)
                    d[mt][nt][x] = (float)di[mt][nt][x] * KAPPA;
    }

    // ---- bf16 phase: stages 32..63 ----
    for (int st = 32; st < NSTG; st++) {
        CP_WAIT2();
        __syncthreads();
        if (st + 3 < NSTG) {
            uint32_t sb = smem + ((st + 3) & 3) * 16384;
            uint32_t off = stage_off(st + 3);
#pragma unroll
            for (int i = 0; i < 2; i++) {
                cp_async16(sb + so[i],        Abase + (size_t)lr[i] * ROWB + off + lc[i] * 16);
                cp_async16(sb + 8192 + so[i], Wbase + (size_t)lr[i] * ROWB + off + lc[i] * 16);
            }
        }
        CP_COMMIT();

        uint32_t base = smem + (st & 3) * 16384;
#pragma unroll
        for (int s16 = 0; s16 < 2; s16++) {
            int ch = s16 * 2 + hib;
            uint32_t a[4][4], bb[2][4];
#pragma unroll
            for (int mt = 0; mt < 4; mt++)
                ldmatrix_x4(a[mt], base + a_off[mt] + ((ch ^ a_sw[mt]) << 4));
#pragma unroll
            for (int bp = 0; bp < 2; bp++)
                ldmatrix_x4(bb[bp], base + b_off[bp] + ((ch ^ b_sw[bp]) << 4));
#pragma unroll
            for (int mt = 0; mt < 4; mt++)
#pragma unroll
                for (int nt = 0; nt < 4; nt++)
                    mma_bf16(d[mt][nt], a[mt],
                             bb[nt >> 1][nt & 1],
                             bb[nt >> 1][(nt & 1) + 2]);
        }
    }

    const int ncol0 = n0 + wn * 32 + (lane & 3) * 2;
    const int mrow0 = m0 + wm * 64 + (lane >> 2);
#pragma unroll
    for (int nt = 0; nt < 4; nt++) {
        float2 bv = *(const float2*)(bias + ncol0 + nt * 8);
#pragma unroll
        for (int mt = 0; mt < 4; mt++) {
            int r1 = mrow0 + mt * 16;
            float v0 = (d[mt][nt][0] + bv.x) * oscale;
            float v1 = (d[mt][nt][1] + bv.y) * oscale;
            float v2 = (d[mt][nt][2] + bv.x) * oscale;
            float v3 = (d[mt][nt][3] + bv.y) * oscale;
            if (OSPLIT) {
                __nv_bfloat16 h0 = __float2bfloat16(v0), h1 = __float2bfloat16(v1);
                __nv_bfloat16 h2 = __float2bfloat16(v2), h3 = __float2bfloat16(v3);
                uint32_t hi0 = pack_bf16x2(v0, v1);
                uint32_t hi1 = pack_bf16x2(v2, v3);
                uint32_t lo0 = pack_bf16x2(v0 - __bfloat162float(h0),
                                           v1 - __bfloat162float(h1));
                uint32_t lo1 = pack_bf16x2(v2 - __bfloat162float(h2),
                                           v3 - __bfloat162float(h3));
                size_t p0 = (size_t)r1 * DD + ncol0 + nt * 8;
                size_t p1 = (size_t)(r1 + 8) * DD + ncol0 + nt * 8;
                *(uint32_t*)(Chi + p0) = hi0;
                *(uint32_t*)(Clo + p0) = lo0;
                *(uint32_t*)(Chi + p1) = hi1;
                *(uint32_t*)(Clo + p1) = lo1;
            } else {
                *(float2*)(C + (size_t)r1 * DD + ncol0 + nt * 8) = make_float2(v0, v1);
                *(float2*)(C + (size_t)(r1 + 8) * DD + ncol0 + nt * 8) = make_float2(v2, v3);
            }
        }
    }
}

__global__ __launch_bounds__(256, 2)
void gemm_qkv_kernel(const float* __restrict__ bq,
                     const float* __restrict__ bk,
                     const float* __restrict__ bv)
{
    extern __shared__ char smem_raw[];
    const int z = blockIdx.z;
    const char* A2 = (z == 0) ? g_a2q : (z == 1) ? g_a2k : g_a2v;
    const char* W2 = (z == 0) ? g_w2q : (z == 1) ? g_w2k : g_w2v;
    const float* bias = (z == 0) ? bq : (z == 1) ? bk : bv;
    __nv_bfloat16* Chi = (z == 0) ? g_qh : (z == 1) ? g_kh : g_vh;
    __nv_bfloat16* Clo = (z == 0) ? g_ql : (z == 1) ? g_kl : g_vl;
    float oscale = (z == 0) ? 0.125f : 1.0f;
    gemm_body<1>(A2, W2, bias, nullptr, Chi, Clo, oscale, smem_raw);
}

__global__ __launch_bounds__(256, 2)
void gemm_o_kernel(const float* __restrict__ bo, float* __restrict__ C)
{
    extern __shared__ char smem_raw[];
    gemm_body<0>(g_a2o, g_w2o, bo, C, nullptr, nullptr, 1.0f, smem_raw);
}

// ---------------------------------------------------------------------------
// Tensor-core windowed flash attention (R12 math) — epilogue emits the
// [bf16hi | al_i8 | a_i8] operand layout for the O-projection.
// ---------------------------------------------------------------------------
#define ATT_SMEM (6 * 8192)

__global__ __launch_bounds__(128, 3)
void attn_tc_kernel()
{
    extern __shared__ __nv_bfloat16 smb[];
    const uint32_t sQh = smem_u32(smb);
    const uint32_t sQl = sQh + 8192;
    const uint32_t sKh = sQh + 16384;
    const uint32_t sKl = sQh + 24576;
    const uint32_t sVh = sQh + 32768;
    const uint32_t sVl = sQh + 40960;

    const int tid = threadIdx.x;
    const int w = tid >> 5;
    const int lane = tid & 31;
    const int lane15 = lane & 15;
    const int hib = lane >> 4;
    const int qt = blockIdx.x;
    const int bh = blockIdx.y;
    const int b = bh >> 4;
    const int h = bh & 15;
    const int q0 = qt * 64;

    const size_t gbase = (size_t)(b * SS) * DD + h * DHH;

#pragma unroll
    for (int t = 0; t < 4; t++) {
        int q = tid + t * 128;
        int row = q >> 3, ch = q & 7;
        uint32_t off = row * 128 + ((ch ^ (row & 7)) << 4);
        cp_async16(sQh + off, g_qh + gbase + (size_t)(q0 + row) * DD + ch * 8);
        cp_async16(sQl + off, g_ql + gbase + (size_t)(q0 + row) * DD + ch * 8);
    }
    CP_COMMIT();
    CP_WAIT0();
    __syncthreads();

    uint32_t qh[4][4], ql[4][4];
    {
        int ar = w * 16 + lane15;
#pragma unroll
        for (int kc = 0; kc < 4; kc++) {
            uint32_t off = ar * 128 + (((kc * 2 + hib) ^ (ar & 7)) << 4);
            ldmatrix_x4(qh[kc], sQh + off);
            ldmatrix_x4(ql[kc], sQl + off);
        }
    }

    const int r0 = q0 + w * 16 + (lane >> 2);
    const int r1 = r0 + 8;

    float o[8][4];
#pragma unroll
    for (int j = 0; j < 8; j++)
#pragma unroll
        for (int x = 0; x < 4; x++) o[j][x] = 0.f;
    float m0r = -1e30f, m1r = -1e30f, l0r = 0.f, l1r = 0.f;

    for (int kb = 0; kb < 5; kb++) {
        int kstart = q0 - 256 + kb * 64;
        if (kstart < 0) continue;

        int jlo = 0, jhi = 8, klo = 0, khi = 4;
        if (kb == 4)      { jhi = 2 * w + 2; khi = w + 1; }
        else if (kb == 0) { jlo = 2 * w;     klo = w; }

        __syncthreads();
#pragma unroll
        for (int t = 0; t < 4; t++) {
            int q = tid + t * 128;
            int row = q >> 3, ch = q & 7;
            uint32_t off = row * 128 + ((ch ^ (row & 7)) << 4);
            size_t gs = gbase + (size_t)(kstart + row) * DD + ch * 8;
            cp_async16(sKh + off, g_kh + gs);
            cp_async16(sKl + off, g_kl + gs);
            cp_async16(sVh + off, g_vh + gs);
            cp_async16(sVl + off, g_vl + gs);
        }
        CP_COMMIT();
        CP_WAIT0();
        __syncthreads();

        float s[8][4];
#pragma unroll
        for (int j = 0; j < 8; j++)
#pragma unroll
            for (int x = 0; x < 4; x++) s[j][x] = 0.f;

#pragma unroll
        for (int kc = 0; kc < 4; kc++) {
            uint32_t kh[4][4], kl[4][4];
#pragma unroll
            for (int ng = 0; ng < 4; ng++) {
                if (ng < (jlo >> 1) || ng > ((jhi - 1) >> 1)) continue;
                int br = ng * 16 + lane15;
                uint32_t off = br * 128 + (((kc * 2 + hib) ^ (br & 7)) << 4);
                ldmatrix_x4(kh[ng], sKh + off);
                ldmatrix_x4(kl[ng], sKl + off);
            }
#pragma unroll
            for (int j = 0; j < 8; j++) {
                if (j < jlo || j >= jhi) continue;
                uint32_t b0h = kh[j >> 1][j & 1], b1h = kh[j >> 1][(j & 1) + 2];
                uint32_t b0l = kl[j >> 1][j & 1], b1l = kl[j >> 1][(j & 1) + 2];
                mma_bf16(s[j], qh[kc], b0h, b1h);
                mma_bf16(s[j], ql[kc], b0h, b1h);
                mma_bf16(s[j], qh[kc], b0l, b1l);
            }
        }

        const int cb = kstart + 2 * (lane & 3);
#pragma unroll
        for (int j = 0; j < 8; j++) {
            int c0 = cb + 8 * j, c1 = c0 + 1;
            if (!(c0 <= r0 && c0 >= r0 - (WINDOW - 1))) s[j][0] = -1e4f;
            if (!(c1 <= r0 && c1 >= r0 - (WINDOW - 1))) s[j][1] = -1e4f;
            if (!(c0 <= r1 && c0 >= r1 - (WINDOW - 1))) s[j][2] = -1e4f;
            if (!(c1 <= r1 && c1 >= r1 - (WINDOW - 1))) s[j][3] = -1e4f;
        }
        float ml0 = -1e30f, ml1 = -1e30f;
#pragma unroll
        for (int j = 0; j < 8; j++) {
            ml0 = fmaxf(ml0, fmaxf(s[j][0], s[j][1]));
            ml1 = fmaxf(ml1, fmaxf(s[j][2], s[j][3]));
        }
        ml0 = fmaxf(ml0, __shfl_xor_sync(0xffffffffu, ml0, 1));
        ml0 = fmaxf(ml0, __shfl_xor_sync(0xffffffffu, ml0, 2));
        ml1 = fmaxf(ml1, __shfl_xor_sync(0xffffffffu, ml1, 1));
        ml1 = fmaxf(ml1, __shfl_xor_sync(0xffffffffu, ml1, 2));
        float mn0 = fmaxf(m0r, ml0), mn1 = fmaxf(m1r, ml1);
        float fac0 = __expf(m0r - mn0), fac1 = __expf(m1r - mn1);
        float ps0 = 0.f, ps1 = 0.f;
#pragma unroll
        for (int j = 0; j < 8; j++) {
            s[j][0] = __expf(s[j][0] - mn0);
            s[j][1] = __expf(s[j][1] - mn0);
            s[j][2] = __expf(s[j][2] - mn1);
            s[j][3] = __expf(s[j][3] - mn1);
            ps0 += s[j][0] + s[j][1];
            ps1 += s[j][2] + s[j][3];
        }
        ps0 += __shfl_xor_sync(0xffffffffu, ps0, 1);
        ps0 += __shfl_xor_sync(0xffffffffu, ps0, 2);
        ps1 += __shfl_xor_sync(0xffffffffu, ps1, 1);
        ps1 += __shfl_xor_sync(0xffffffffu, ps1, 2);
        l0r = l0r * fac0 + ps0;  m0r = mn0;
        l1r = l1r * fac1 + ps1;  m1r = mn1;
#pragma unroll
        for (int j = 0; j < 8; j++) {
            o[j][0] *= fac0; o[j][1] *= fac0;
            o[j][2] *= fac1; o[j][3] *= fac1;
        }

        uint32_t phi[4][4], plo[4][4];
#pragma unroll
        for (int kc = 0; kc < 4; kc++) {
            if (kc < klo || kc >= khi) continue;
#pragma unroll
            for (int hx = 0; hx < 4; hx++) {
                float x0 = s[2 * kc + (hx >> 1)][(hx & 1) * 2];
                float x1 = s[2 * kc + (hx >> 1)][(hx & 1) * 2 + 1];
                __nv_bfloat16 hh0 = __float2bfloat16(x0);
                __nv_bfloat16 hh1 = __float2bfloat16(x1);
                phi[kc][hx] = pack_bf16x2(x0, x1);
                plo[kc][hx] = pack_bf16x2(x0 - __bfloat162float(hh0),
                                          x1 - __bfloat162float(hh1));
            }
        }

#pragma unroll
        for (int kc = 0; kc < 4; kc++) {
            if (kc < klo || kc >= khi) continue;
            uint32_t vh[4][4], vl[4][4];
            int vr = kc * 16 + lane15;
#pragma unroll
            for (int ng = 0; ng < 4; ng++) {
                uint32_t off = vr * 128 + (((ng * 2 + hib) ^ (vr & 7)) << 4);
                ldmatrix_x4_trans(vh[ng], sVh + off);
                ldmatrix_x4_trans(vl[ng], sVl + off);
            }
#pragma unroll
            for (int j = 0; j < 8; j++) {
                uint32_t b0h = vh[j >> 1][(j & 1) * 2];
                uint32_t b1h = vh[j >> 1][(j & 1) * 2 + 1];
                uint32_t b0l = vl[j >> 1][(j & 1) * 2];
                uint32_t b1l = vl[j >> 1][(j & 1) * 2 + 1];
                mma_bf16(o[j], phi[kc], b0h, b1h);
                mma_bf16(o[j], plo[kc], b0h, b1h);
                mma_bf16(o[j], phi[kc], b0l, b1l);
            }
        }
    }

    // ---- epilogue: /l, emit [bf16hi | al_i8 | a_i8] rows into g_a2o ----
    float inv0 = 1.f / l0r, inv1 = 1.f / l1r;
    const int colbase = h * DHH + 2 * (lane & 3);
    char* rb0 = g_a2o + (size_t)(b * SS + r0) * ROWB;
    char* rb1 = g_a2o + (size_t)(b * SS + r1) * ROWB;
#pragma unroll
    for (int j = 0; j < 8; j++) {
        int col = colbase + 8 * j;
        float a0 = o[j][0] * inv0, a1 = o[j][1] * inv0;
        float a2 = o[j][2] * inv1, a3 = o[j][3] * inv1;

        __nv_bfloat16 h0 = __float2bfloat16(a0), h1 = __float2bfloat16(a1);
        __nv_bfloat16 h2 = __float2bfloat16(a2), h3 = __float2bfloat16(a3);
        *(uint32_t*)(rb0 + 2 * col) = pack_bf16x2(a0, a1);
        *(uint32_t*)(rb1 + 2 * col) = pack_bf16x2(a2, a3);
        float al0 = a0 - __bfloat162float(h0), al1 = a1 - __bfloat162float(h1);
        float al2 = a2 - __bfloat162float(h2), al3 = a3 - __bfloat162float(h3);
        *(uint16_t*)(rb0 + 2048 + col) =
            (uint16_t)((sat8(al0, INV_AL) & 255) | ((sat8(al1, INV_AL) & 255) << 8));
        *(uint16_t*)(rb1 + 2048 + col) =
            (uint16_t)((sat8(al2, INV_AL) & 255) | ((sat8(al3, INV_AL) & 255) << 8));
        *(uint16_t*)(rb0 + 3072 + col) =
            (uint16_t)((sat8(a0, INV_A) & 255) | ((sat8(a1, INV_A) & 255) << 8));
        *(uint16_t*)(rb1 + 3072 + col) =
            (uint16_t)((sat8(a2, INV_A) & 255) | ((sat8(a3, INV_A) & 255) << 8));
    }
}

// ---------------------------------------------------------------------------
extern "C" void kernel_launch(void* const* d_in, const int* in_sizes, int n_in,
                              void* d_out, int out_size)
{
    (void)in_sizes; (void)n_in; (void)out_size;
    const float* query = (const float*)d_in[0];
    const float* key   = (const float*)d_in[1];
    const float* value = (const float*)d_in[2];
    const float* Wq = (const float*)d_in[3];
    const float* bq = (const float*)d_in[4];
    const float* Wk = (const float*)d_in[5];
    const float* bk = (const float*)d_in[6];
    const float* Wv = (const float*)d_in[7];
    const float* bv = (const float*)d_in[8];
    const float* Wo = (const float*)d_in[9];
    const float* bo = (const float*)d_in[10];
    float* out = (float*)d_out;

    const int SMEM_GEMM = 4 * 16384;
    cudaFuncSetAttribute(gemm_qkv_kernel,
                         cudaFuncAttributeMaxDynamicSharedMemorySize, SMEM_GEMM);
    cudaFuncSetAttribute(gemm_o_kernel,
                         cudaFuncAttributeMaxDynamicSharedMemorySize, SMEM_GEMM);
    cudaFuncSetAttribute(attn_tc_kernel,
                         cudaFuncAttributeMaxDynamicSharedMemorySize, ATT_SMEM);

    prep_kernel<<<dim3(MM, 7), 256>>>(query, key, value, Wq, Wk, Wv, Wo);

    gemm_qkv_kernel<<<dim3(DD / 128, MM / 128, 3), 256, SMEM_GEMM>>>(bq, bk, bv);

    attn_tc_kernel<<<dim3(SS / 64, BB * HH), 128, ATT_SMEM>>>();

    gemm_o_kernel<<<dim3(DD / 128, MM / 128), 256, SMEM_GEMM>>>(bo, out);
}

// round 17
// speedup vs baseline: 1.7477x; 1.7477x over previous
#include <cuda_runtime.h>
#include <cuda_bf16.h>
#include <cuda_fp16.h>
#include <cstdint>
#include <cstddef>

#define BB 2
#define SS 2048
#define DD 1024
#define HH 16
#define DHH 64
#define WINDOW 256
#define MM (BB * SS)        // 4096 activation rows
#define ROWB 6144           // bytes/row: [bf16 hi 2048 | f16 r1 2048 | f16 r2 2048]
#define NSTG 96             // 64 f16-corr stages + 32 bf16 hi*hi stages

// ---------------- scratch (__device__ globals; no allocs allowed) ----------
__device__ __nv_bfloat16 g_qh[(size_t)MM * DD];   // projected Q hi (pre-scaled 0.125)
__device__ __nv_bfloat16 g_ql[(size_t)MM * DD];
__device__ __nv_bfloat16 g_kh[(size_t)MM * DD];
__device__ __nv_bfloat16 g_kl[(size_t)MM * DD];
__device__ __nv_bfloat16 g_vh[(size_t)MM * DD];
__device__ __nv_bfloat16 g_vl[(size_t)MM * DD];
// A rows: [ah_bf16 | f16(al*256) | f16(ah)]
__device__ char g_a2q[(size_t)MM * ROWB];
__device__ char g_a2k[(size_t)MM * ROWB];
__device__ char g_a2v[(size_t)MM * ROWB];
__device__ char g_a2o[(size_t)MM * ROWB];
// W rows: [wh_bf16 | f16(wh) | f16(wl*256)]
__device__ char g_w2q[(size_t)DD * ROWB];
__device__ char g_w2k[(size_t)DD * ROWB];
__device__ char g_w2v[(size_t)DD * ROWB];
__device__ char g_w2o[(size_t)DD * ROWB];

// ---------------- PTX helpers ----------------------------------------------
__device__ __forceinline__ uint32_t smem_u32(const void* p) {
    uint32_t a;
    asm("{ .reg .u64 t; cvta.to.shared.u64 t, %1; cvt.u32.u64 %0, t; }"
        : "=r"(a) : "l"(p));
    return a;
}
__device__ __forceinline__ void cp_async16(uint32_t saddr, const void* gaddr) {
    asm volatile("cp.async.cg.shared.global [%0], [%1], 16;"
                 :: "r"(saddr), "l"(gaddr));
}
#define CP_COMMIT() asm volatile("cp.async.commit_group;" ::: "memory")
#define CP_WAIT2()  asm volatile("cp.async.wait_group 2;" ::: "memory")
#define CP_WAIT0()  asm volatile("cp.async.wait_group 0;" ::: "memory")

__device__ __forceinline__ void ldmatrix_x4(uint32_t* r, uint32_t addr) {
    asm volatile("ldmatrix.sync.aligned.m8n8.x4.shared.b16 {%0,%1,%2,%3}, [%4];"
                 : "=r"(r[0]), "=r"(r[1]), "=r"(r[2]), "=r"(r[3]) : "r"(addr));
}
__device__ __forceinline__ void ldmatrix_x4_trans(uint32_t* r, uint32_t addr) {
    asm volatile("ldmatrix.sync.aligned.m8n8.x4.trans.shared.b16 {%0,%1,%2,%3}, [%4];"
                 : "=r"(r[0]), "=r"(r[1]), "=r"(r[2]), "=r"(r[3]) : "r"(addr));
}
__device__ __forceinline__ void mma_bf16(float* d, const uint32_t* a,
                                         uint32_t b0, uint32_t b1) {
    asm volatile(
        "mma.sync.aligned.m16n8k16.row.col.f32.bf16.bf16.f32 "
        "{%0,%1,%2,%3}, {%4,%5,%6,%7}, {%8,%9}, {%0,%1,%2,%3};"
        : "+f"(d[0]), "+f"(d[1]), "+f"(d[2]), "+f"(d[3])
        : "r"(a[0]), "r"(a[1]), "r"(a[2]), "r"(a[3]), "r"(b0), "r"(b1));
}
// f16 x f16 -> f16 accumulator (2-reg C fragment). Testing double-rate theory.
__device__ __forceinline__ void mma_f16a(uint32_t* d, const uint32_t* a,
                                         uint32_t b0, uint32_t b1) {
    asm volatile(
        "mma.sync.aligned.m16n8k16.row.col.f16.f16.f16.f16 "
        "{%0,%1}, {%2,%3,%4,%5}, {%6,%7}, {%0,%1};"
        : "+r"(d[0]), "+r"(d[1])
        : "r"(a[0]), "r"(a[1]), "r"(a[2]), "r"(a[3]), "r"(b0), "r"(b1));
}
__device__ __forceinline__ uint32_t pack_bf16x2(float a, float b) {
    __nv_bfloat162 t;
    t.x = __float2bfloat16(a);
    t.y = __float2bfloat16(b);
    return *(uint32_t*)&t;
}
__device__ __forceinline__ uint32_t pack_f16x2(float a, float b) {
    __half2 t;
    t.x = __float2half(a);
    t.y = __float2half(b);
    return *(uint32_t*)&t;
}

// stage -> byte offset within operand row (64 B per stage):
//   s 0..31  -> 2048 + s*64       (A: al*256 f16   | W: wh f16)     term2
//   s 32..63 -> 4096 + (s-32)*64  (A: ah f16       | W: wl*256 f16) term3
//   s 64..95 -> (s-64)*64         (bf16 hi block)                   term1
__device__ __forceinline__ uint32_t stage_off(int s) {
    return (s < 64) ? (2048u + (uint32_t)s * 64u)
                    : ((uint32_t)(s - 64) * 64u);
}

// ---------------------------------------------------------------------------
// Fused prep: all 7 operand conversions in one launch.
// grid (4096, 7): y=0..3 -> Wq/Wk/Wv/Wo ; y=4..6 -> query/key/value.
// ---------------------------------------------------------------------------
__global__ void prep_kernel(const float* __restrict__ query,
                            const float* __restrict__ key,
                            const float* __restrict__ value,
                            const float* __restrict__ Wq,
                            const float* __restrict__ Wk,
                            const float* __restrict__ Wv,
                            const float* __restrict__ Wo)
{
    const int y = blockIdx.y;
    const int row = blockIdx.x;
    const float* in;
    char* out;
    bool amode;
    if (y < 4) {
        if (row >= DD) return;
        amode = false;
        in  = (y == 0) ? Wq : (y == 1) ? Wk : (y == 2) ? Wv : Wo;
        out = (y == 0) ? g_w2q : (y == 1) ? g_w2k : (y == 2) ? g_w2v : g_w2o;
    } else {
        amode = true;
        in  = (y == 4) ? query : (y == 5) ? key : value;
        out = (y == 4) ? g_a2q : (y == 5) ? g_a2k : g_a2v;
    }
    const int c4 = threadIdx.x;            // 0..255, covers cols 4c4..4c4+3
    float4 f = ((const float4*)in)[(size_t)row * 256 + c4];

    __nv_bfloat16 h0 = __float2bfloat16(f.x);
    __nv_bfloat16 h1 = __float2bfloat16(f.y);
    __nv_bfloat16 h2 = __float2bfloat16(f.z);
    __nv_bfloat16 h3 = __float2bfloat16(f.w);
    float hf0 = __bfloat162float(h0), hf1 = __bfloat162float(h1);
    float hf2 = __bfloat162float(h2), hf3 = __bfloat162float(h3);
    float r0 = f.x - hf0, r1 = f.y - hf1, r2 = f.z - hf2, r3 = f.w - hf3;

    __nv_bfloat162 hp0, hp1;
    hp0.x = h0; hp0.y = h1; hp1.x = h2; hp1.y = h3;

    char* rb = out + (size_t)row * ROWB;
    ((uint32_t*)(rb + c4 * 8))[0] = *(uint32_t*)&hp0;
    ((uint32_t*)(rb + c4 * 8))[1] = *(uint32_t*)&hp1;

    uint32_t r1a, r1b, r2a, r2b;
    if (amode) {
        // region1: f16(al*256), region2: f16(ah)
        r1a = pack_f16x2(r0 * 256.f, r1 * 256.f);
        r1b = pack_f16x2(r2 * 256.f, r3 * 256.f);
        r2a = pack_f16x2(hf0, hf1);
        r2b = pack_f16x2(hf2, hf3);
    } else {
        // region1: f16(wh), region2: f16(wl*256)
        r1a = pack_f16x2(hf0, hf1);
        r1b = pack_f16x2(hf2, hf3);
        r2a = pack_f16x2(r0 * 256.f, r1 * 256.f);
        r2b = pack_f16x2(r2 * 256.f, r3 * 256.f);
    }
    ((uint32_t*)(rb + 2048 + c4 * 8))[0] = r1a;
    ((uint32_t*)(rb + 2048 + c4 * 8))[1] = r1b;
    ((uint32_t*)(rb + 4096 + c4 * 8))[0] = r2a;
    ((uint32_t*)(rb + 4096 + c4 * 8))[1] = r2b;
}

// ---------------------------------------------------------------------------
// GEMM: C = A @ W^T + bias. CTA 128x128, 8 warps (2Mx4N), warp tile 64x32.
// Stages 0..63: f16 corrections (al*256*wh + ah*wl*256, shared f16 accum);
// stages 64..95: bf16 hi*hi (f32 accum). Fold d = 2^-8 * f16acc.
// ---------------------------------------------------------------------------
template <int OSPLIT>
__device__ __forceinline__ void gemm_body(
    const char* __restrict__ A2, const char* __restrict__ W2,
    const float* __restrict__ bias, float* __restrict__ C,
    __nv_bfloat16* __restrict__ Chi, __nv_bfloat16* __restrict__ Clo,
    float oscale, char* smem_raw)
{
    const uint32_t smem = smem_u32(smem_raw);

    const int tid  = threadIdx.x;          // 0..255
    const int wid  = tid >> 5;
    const int lane = tid & 31;
    const int wm = wid & 1;
    const int wn = wid >> 1;               // 0..3
    const int n0 = blockIdx.x * 128;
    const int m0 = blockIdx.y * 128;

    const char* Abase = A2 + (size_t)m0 * ROWB;
    const char* Wbase = W2 + (size_t)n0 * ROWB;

    // cp.async: 1024 16B chunks/stage (A 512 + B 512), 4 per thread
    int lr[2], lc[2];
    uint32_t so[2];
#pragma unroll
    for (int i = 0; i < 2; i++) {
        int cl = tid + i * 256;
        lr[i] = cl >> 2;                   // 0..127
        lc[i] = cl & 3;
        so[i] = lr[i] * 64 + ((lc[i] ^ ((lr[i] >> 1) & 3)) << 4);
    }

    const int lane15 = lane & 15;
    const int hib = lane >> 4;
    uint32_t a_off[4], b_off[2];
    int a_sw[4], b_sw[2];
#pragma unroll
    for (int mt = 0; mt < 4; mt++) {
        int r = wm * 64 + mt * 16 + lane15;
        a_off[mt] = r * 64;
        a_sw[mt] = (r >> 1) & 3;
    }
#pragma unroll
    for (int bp = 0; bp < 2; bp++) {
        int r = wn * 32 + bp * 16 + lane15;
        b_off[bp] = 8192 + r * 64;
        b_sw[bp] = (r >> 1) & 3;
    }

    // prologue: prefetch stages 0..2
#pragma unroll
    for (int st = 0; st < 3; st++) {
        uint32_t sb = smem + (st & 3) * 16384;
        uint32_t off = stage_off(st);
#pragma unroll
        for (int i = 0; i < 2; i++) {
            cp_async16(sb + so[i],        Abase + (size_t)lr[i] * ROWB + off + lc[i] * 16);
            cp_async16(sb + 8192 + so[i], Wbase + (size_t)lr[i] * ROWB + off + lc[i] * 16);
        }
        CP_COMMIT();
    }

    float d[4][4][4];
    {
        uint32_t dh[4][4][2];              // packed f16x2 accumulators
#pragma unroll
        for (int mt = 0; mt < 4; mt++)
#pragma unroll
            for (int nt = 0; nt < 4; nt++) {
                dh[mt][nt][0] = 0u;
                dh[mt][nt][1] = 0u;
            }

        // ---- f16 correction phase: stages 0..63 ----
        for (int st = 0; st < 64; st++) {
            CP_WAIT2();
            __syncthreads();
            {
                uint32_t sb = smem + ((st + 3) & 3) * 16384;
                uint32_t off = stage_off(st + 3);
#pragma unroll
                for (int i = 0; i < 2; i++) {
                    cp_async16(sb + so[i],        Abase + (size_t)lr[i] * ROWB + off + lc[i] * 16);
                    cp_async16(sb + 8192 + so[i], Wbase + (size_t)lr[i] * ROWB + off + lc[i] * 16);
                }
            }
            CP_COMMIT();

            uint32_t base = smem + (st & 3) * 16384;
#pragma unroll
            for (int s16 = 0; s16 < 2; s16++) {
                int ch = s16 * 2 + hib;
                uint32_t a[4][4], bb[2][4];
#pragma unroll
                for (int mt = 0; mt < 4; mt++)
                    ldmatrix_x4(a[mt], base + a_off[mt] + ((ch ^ a_sw[mt]) << 4));
#pragma unroll
                for (int bp = 0; bp < 2; bp++)
                    ldmatrix_x4(bb[bp], base + b_off[bp] + ((ch ^ b_sw[bp]) << 4));
#pragma unroll
                for (int mt = 0; mt < 4; mt++)
#pragma unroll
                    for (int nt = 0; nt < 4; nt++)
                        mma_f16a(dh[mt][nt], a[mt],
                                 bb[nt >> 1][nt & 1],
                                 bb[nt >> 1][(nt & 1) + 2]);
            }
        }

        // fold f16 corrections into f32 accumulators (x 2^-8)
#pragma unroll
        for (int mt = 0; mt < 4; mt++)
#pragma unroll
            for (int nt = 0; nt < 4; nt++) {
                __half2 p0 = *(__half2*)&dh[mt][nt][0];
                __half2 p1 = *(__half2*)&dh[mt][nt][1];
                d[mt][nt][0] = __half2float(p0.x) * 0.00390625f;
                d[mt][nt][1] = __half2float(p0.y) * 0.00390625f;
                d[mt][nt][2] = __half2float(p1.x) * 0.00390625f;
                d[mt][nt][3] = __half2float(p1.y) * 0.00390625f;
            }
    }

    // ---- bf16 hi*hi phase: stages 64..95 ----
    for (int st = 64; st < NSTG; st++) {
        CP_WAIT2();
        __syncthreads();
        if (st + 3 < NSTG) {
            uint32_t sb = smem + ((st + 3) & 3) * 16384;
            uint32_t off = stage_off(st + 3);
#pragma unroll
            for (int i = 0; i < 2; i++) {
                cp_async16(sb + so[i],        Abase + (size_t)lr[i] * ROWB + off + lc[i] * 16);
                cp_async16(sb + 8192 + so[i], Wbase + (size_t)lr[i] * ROWB + off + lc[i] * 16);
            }
        }
        CP_COMMIT();

        uint32_t base = smem + (st & 3) * 16384;
#pragma unroll
        for (int s16 = 0; s16 < 2; s16++) {
            int ch = s16 * 2 + hib;
            uint32_t a[4][4], bb[2][4];
#pragma unroll
            for (int mt = 0; mt < 4; mt++)
                ldmatrix_x4(a[mt], base + a_off[mt] + ((ch ^ a_sw[mt]) << 4));
#pragma unroll
            for (int bp = 0; bp < 2; bp++)
                ldmatrix_x4(bb[bp], base + b_off[bp] + ((ch ^ b_sw[bp]) << 4));
#pragma unroll
            for (int mt = 0; mt < 4; mt++)
#pragma unroll
                for (int nt = 0; nt < 4; nt++)
                    mma_bf16(d[mt][nt], a[mt],
                             bb[nt >> 1][nt & 1],
                             bb[nt >> 1][(nt & 1) + 2]);
        }
    }

    const int ncol0 = n0 + wn * 32 + (lane & 3) * 2;
    const int mrow0 = m0 + wm * 64 + (lane >> 2);
#pragma unroll
    for (int nt = 0; nt < 4; nt++) {
        float2 bv = *(const float2*)(bias + ncol0 + nt * 8);
#pragma unroll
        for (int mt = 0; mt < 4; mt++) {
            int r1 = mrow0 + mt * 16;
            float v0 = (d[mt][nt][0] + bv.x) * oscale;
            float v1 = (d[mt][nt][1] + bv.y) * oscale;
            float v2 = (d[mt][nt][2] + bv.x) * oscale;
            float v3 = (d[mt][nt][3] + bv.y) * oscale;
            if (OSPLIT) {
                __nv_bfloat16 h0 = __float2bfloat16(v0), h1 = __float2bfloat16(v1);
                __nv_bfloat16 h2 = __float2bfloat16(v2), h3 = __float2bfloat16(v3);
                uint32_t hi0 = pack_bf16x2(v0, v1);
                uint32_t hi1 = pack_bf16x2(v2, v3);
                uint32_t lo0 = pack_bf16x2(v0 - __bfloat162float(h0),
                                           v1 - __bfloat162float(h1));
                uint32_t lo1 = pack_bf16x2(v2 - __bfloat162float(h2),
                                           v3 - __bfloat162float(h3));
                size_t p0 = (size_t)r1 * DD + ncol0 + nt * 8;
                size_t p1 = (size_t)(r1 + 8) * DD + ncol0 + nt * 8;
                *(uint32_t*)(Chi + p0) = hi0;
                *(uint32_t*)(Clo + p0) = lo0;
                *(uint32_t*)(Chi + p1) = hi1;
                *(uint32_t*)(Clo + p1) = lo1;
            } else {
                *(float2*)(C + (size_t)r1 * DD + ncol0 + nt * 8) = make_float2(v0, v1);
                *(float2*)(C + (size_t)(r1 + 8) * DD + ncol0 + nt * 8) = make_float2(v2, v3);
            }
        }
    }
}

__global__ __launch_bounds__(256, 2)
void gemm_qkv_kernel(const float* __restrict__ bq,
                     const float* __restrict__ bk,
                     const float* __restrict__ bv)
{
    extern __shared__ char smem_raw[];
    const int z = blockIdx.z;
    const char* A2 = (z == 0) ? g_a2q : (z == 1) ? g_a2k : g_a2v;
    const char* W2 = (z == 0) ? g_w2q : (z == 1) ? g_w2k : g_w2v;
    const float* bias = (z == 0) ? bq : (z == 1) ? bk : bv;
    __nv_bfloat16* Chi = (z == 0) ? g_qh : (z == 1) ? g_kh : g_vh;
    __nv_bfloat16* Clo = (z == 0) ? g_ql : (z == 1) ? g_kl : g_vl;
    float oscale = (z == 0) ? 0.125f : 1.0f;
    gemm_body<1>(A2, W2, bias, nullptr, Chi, Clo, oscale, smem_raw);
}

__global__ __launch_bounds__(256, 2)
void gemm_o_kernel(const float* __restrict__ bo, float* __restrict__ C)
{
    extern __shared__ char smem_raw[];
    gemm_body<0>(g_a2o, g_w2o, bo, C, nullptr, nullptr, 1.0f, smem_raw);
}

// ---------------------------------------------------------------------------
// Tensor-core windowed flash attention (R12 math) — epilogue emits the
// [bf16 hi | f16(lo*256) | f16(hi)] operand layout for the O-projection.
// ---------------------------------------------------------------------------
#define ATT_SMEM (6 * 8192)

__global__ __launch_bounds__(128, 3)
void attn_tc_kernel()
{
    extern __shared__ __nv_bfloat16 smb[];
    const uint32_t sQh = smem_u32(smb);
    const uint32_t sQl = sQh + 8192;
    const uint32_t sKh = sQh + 16384;
    const uint32_t sKl = sQh + 24576;
    const uint32_t sVh = sQh + 32768;
    const uint32_t sVl = sQh + 40960;

    const int tid = threadIdx.x;
    const int w = tid >> 5;
    const int lane = tid & 31;
    const int lane15 = lane & 15;
    const int hib = lane >> 4;
    const int qt = blockIdx.x;
    const int bh = blockIdx.y;
    const int b = bh >> 4;
    const int h = bh & 15;
    const int q0 = qt * 64;

    const size_t gbase = (size_t)(b * SS) * DD + h * DHH;

#pragma unroll
    for (int t = 0; t < 4; t++) {
        int q = tid + t * 128;
        int row = q >> 3, ch = q & 7;
        uint32_t off = row * 128 + ((ch ^ (row & 7)) << 4);
        cp_async16(sQh + off, g_qh + gbase + (size_t)(q0 + row) * DD + ch * 8);
        cp_async16(sQl + off, g_ql + gbase + (size_t)(q0 + row) * DD + ch * 8);
    }
    CP_COMMIT();
    CP_WAIT0();
    __syncthreads();

    uint32_t qh[4][4], ql[4][4];
    {
        int ar = w * 16 + lane15;
#pragma unroll
        for (int kc = 0; kc < 4; kc++) {
            uint32_t off = ar * 128 + (((kc * 2 + hib) ^ (ar & 7)) << 4);
            ldmatrix_x4(qh[kc], sQh + off);
            ldmatrix_x4(ql[kc], sQl + off);
        }
    }

    const int r0 = q0 + w * 16 + (lane >> 2);
    const int r1 = r0 + 8;

    float o[8][4];
#pragma unroll
    for (int j = 0; j < 8; j++)
#pragma unroll
        for (int x = 0; x < 4; x++) o[j][x] = 0.f;
    float m0r = -1e30f, m1r = -1e30f, l0r = 0.f, l1r = 0.f;

    for (int kb = 0; kb < 5; kb++) {
        int kstart = q0 - 256 + kb * 64;
        if (kstart < 0) continue;

        int jlo = 0, jhi = 8, klo = 0, khi = 4;
        if (kb == 4)      { jhi = 2 * w + 2; khi = w + 1; }
        else if (kb == 0) { jlo = 2 * w;     klo = w; }

        __syncthreads();
#pragma unroll
        for (int t = 0; t < 4; t++) {
            int q = tid + t * 128;
            int row = q >> 3, ch = q & 7;
            uint32_t off = row * 128 + ((ch ^ (row & 7)) << 4);
            size_t gs = gbase + (size_t)(kstart + row) * DD + ch * 8;
            cp_async16(sKh + off, g_kh + gs);
            cp_async16(sKl + off, g_kl + gs);
            cp_async16(sVh + off, g_vh + gs);
            cp_async16(sVl + off, g_vl + gs);
        }
        CP_COMMIT();
        CP_WAIT0();
        __syncthreads();

        float s[8][4];
#pragma unroll
        for (int j = 0; j < 8; j++)
#pragma unroll
            for (int x = 0; x < 4; x++) s[j][x] = 0.f;

#pragma unroll
        for (int kc = 0; kc < 4; kc++) {
            uint32_t kh[4][4], kl[4][4];
#pragma unroll
            for (int ng = 0; ng < 4; ng++) {
                if (ng < (jlo >> 1) || ng > ((jhi - 1) >> 1)) continue;
                int br = ng * 16 + lane15;
                uint32_t off = br * 128 + (((kc * 2 + hib) ^ (br & 7)) << 4);
                ldmatrix_x4(kh[ng], sKh + off);
                ldmatrix_x4(kl[ng], sKl + off);
            }
#pragma unroll
            for (int j = 0; j < 8; j++) {
                if (j < jlo || j >= jhi) continue;
                uint32_t b0h = kh[j >> 1][j & 1], b1h = kh[j >> 1][(j & 1) + 2];
                uint32_t b0l = kl[j >> 1][j & 1], b1l = kl[j >> 1][(j & 1) + 2];
                mma_bf16(s[j], qh[kc], b0h, b1h);
                mma_bf16(s[j], ql[kc], b0h, b1h);
                mma_bf16(s[j], qh[kc], b0l, b1l);
            }
        }

        const int cb = kstart + 2 * (lane & 3);
#pragma unroll
        for (int j = 0; j < 8; j++) {
            int c0 = cb + 8 * j, c1 = c0 + 1;
            if (!(c0 <= r0 && c0 >= r0 - (WINDOW - 1))) s[j][0] = -1e4f;
            if (!(c1 <= r0 && c1 >= r0 - (WINDOW - 1))) s[j][1] = -1e4f;
            if (!(c0 <= r1 && c0 >= r1 - (WINDOW - 1))) s[j][2] = -1e4f;
            if (!(c1 <= r1 && c1 >= r1 - (WINDOW - 1))) s[j][3] = -1e4f;
        }
        float ml0 = -1e30f, ml1 = -1e30f;
#pragma unroll
        for (int j = 0; j < 8; j++) {
            ml0 = fmaxf(ml0, fmaxf(s[j][0], s[j][1]));
            ml1 = fmaxf(ml1, fmaxf(s[j][2], s[j][3]));
        }
        ml0 = fmaxf(ml0, __shfl_xor_sync(0xffffffffu, ml0, 1));
        ml0 = fmaxf(ml0, __shfl_xor_sync(0xffffffffu, ml0, 2));
        ml1 = fmaxf(ml1, __shfl_xor_sync(0xffffffffu, ml1, 1));
        ml1 = fmaxf(ml1, __shfl_xor_sync(0xffffffffu, ml1, 2));
        float mn0 = fmaxf(m0r, ml0), mn1 = fmaxf(m1r, ml1);
        float fac0 = __expf(m0r - mn0), fac1 = __expf(m1r - mn1);
        float ps0 = 0.f, ps1 = 0.f;
#pragma unroll
        for (int j = 0; j < 8; j++) {
            s[j][0] = __expf(s[j][0] - mn0);
            s[j][1] = __expf(s[j][1] - mn0);
            s[j][2] = __expf(s[j][2] - mn1);
            s[j][3] = __expf(s[j][3] - mn1);
            ps0 += s[j][0] + s[j][1];
            ps1 += s[j][2] + s[j][3];
        }
        ps0 += __shfl_xor_sync(0xffffffffu, ps0, 1);
        ps0 += __shfl_xor_sync(0xffffffffu, ps0, 2);
        ps1 += __shfl_xor_sync(0xffffffffu, ps1, 1);
        ps1 += __shfl_xor_sync(0xffffffffu, ps1, 2);
        l0r = l0r * fac0 + ps0;  m0r = mn0;
        l1r = l1r * fac1 + ps1;  m1r = mn1;
#pragma unroll
        for (int j = 0; j < 8; j++) {
            o[j][0] *= fac0; o[j][1] *= fac0;
            o[j][2] *= fac1; o[j][3] *= fac1;
        }

        uint32_t phi[4][4], plo[4][4];
#pragma unroll
        for (int kc = 0; kc < 4; kc++) {
            if (kc < klo || kc >= khi) continue;
#pragma unroll
            for (int hx = 0; hx < 4; hx++) {
                float x0 = s[2 * kc + (hx >> 1)][(hx & 1) * 2];
                float x1 = s[2 * kc + (hx >> 1)][(hx & 1) * 2 + 1];
                __nv_bfloat16 hh0 = __float2bfloat16(x0);
                __nv_bfloat16 hh1 = __float2bfloat16(x1);
                phi[kc][hx] = pack_bf16x2(x0, x1);
                plo[kc][hx] = pack_bf16x2(x0 - __bfloat162float(hh0),
                                          x1 - __bfloat162float(hh1));
            }
        }

#pragma unroll
        for (int kc = 0; kc < 4; kc++) {
            if (kc < klo || kc >= khi) continue;
            uint32_t vh[4][4], vl[4][4];
            int vr = kc * 16 + lane15;
#pragma unroll
            for (int ng = 0; ng < 4; ng++) {
                uint32_t off = vr * 128 + (((ng * 2 + hib) ^ (vr & 7)) << 4);
                ldmatrix_x4_trans(vh[ng], sVh + off);
                ldmatrix_x4_trans(vl[ng], sVl + off);
            }
#pragma unroll
            for (int j = 0; j < 8; j++) {
                uint32_t b0h = vh[j >> 1][(j & 1) * 2];
                uint32_t b1h = vh[j >> 1][(j & 1) * 2 + 1];
                uint32_t b0l = vl[j >> 1][(j & 1) * 2];
                uint32_t b1l = vl[j >> 1][(j & 1) * 2 + 1];
                mma_bf16(o[j], phi[kc], b0h, b1h);
                mma_bf16(o[j], plo[kc], b0h, b1h);
                mma_bf16(o[j], phi[kc], b0l, b1l);
            }
        }
    }

    // ---- epilogue: /l, emit [bf16 hi | f16(lo*256) | f16(hi)] into g_a2o ----
    float inv0 = 1.f / l0r, inv1 = 1.f / l1r;
    const int colbase = h * DHH + 2 * (lane & 3);
    char* rb0 = g_a2o + (size_t)(b * SS + r0) * ROWB;
    char* rb1 = g_a2o + (size_t)(b * SS + r1) * ROWB;
#pragma unroll
    for (int j = 0; j < 8; j++) {
        int col = colbase + 8 * j;
        float a0 = o[j][0] * inv0, a1 = o[j][1] * inv0;
        float a2 = o[j][2] * inv1, a3 = o[j][3] * inv1;

        __nv_bfloat16 h0 = __float2bfloat16(a0), h1 = __float2bfloat16(a1);
        __nv_bfloat16 h2 = __float2bfloat16(a2), h3 = __float2bfloat16(a3);
        float hf0 = __bfloat162float(h0), hf1 = __bfloat162float(h1);
        float hf2 = __bfloat162float(h2), hf3 = __bfloat162float(h3);

        *(uint32_t*)(rb0 + 2 * col) = pack_bf16x2(a0, a1);
        *(uint32_t*)(rb1 + 2 * col) = pack_bf16x2(a2, a3);
        *(uint32_t*)(rb0 + 2048 + 2 * col) =
            pack_f16x2((a0 - hf0) * 256.f, (a1 - hf1) * 256.f);
        *(uint32_t*)(rb1 + 2048 + 2 * col) =
            pack_f16x2((a2 - hf2) * 256.f, (a3 - hf3) * 256.f);
        *(uint32_t*)(rb0 + 4096 + 2 * col) = pack_f16x2(hf0, hf1);
        *(uint32_t*)(rb1 + 4096 + 2 * col) = pack_f16x2(hf2, hf3);
    }
}

// ---------------------------------------------------------------------------
extern "C" void kernel_launch(void* const* d_in, const int* in_sizes, int n_in,
                              void* d_out, int out_size)
{
    (void)in_sizes; (void)n_in; (void)out_size;
    const float* query = (const float*)d_in[0];
    const float* key   = (const float*)d_in[1];
    const float* value = (const float*)d_in[2];
    const float* Wq = (const float*)d_in[3];
    const float* bq = (const float*)d_in[4];
    const float* Wk = (const float*)d_in[5];
    const float* bk = (const float*)d_in[6];
    const float* Wv = (const float*)d_in[7];
    const float* bv = (const float*)d_in[8];
    const float* Wo = (const float*)d_in[9];
    const float* bo = (const float*)d_in[10];
    float* out = (float*)d_out;

    const int SMEM_GEMM = 4 * 16384;
    cudaFuncSetAttribute(gemm_qkv_kernel,
                         cudaFuncAttributeMaxDynamicSharedMemorySize, SMEM_GEMM);
    cudaFuncSetAttribute(gemm_o_kernel,
                         cudaFuncAttributeMaxDynamicSharedMemorySize, SMEM_GEMM);
    cudaFuncSetAttribute(attn_tc_kernel,
                         cudaFuncAttributeMaxDynamicSharedMemorySize, ATT_SMEM);

    prep_kernel<<<dim3(MM, 7), 256>>>(query, key, value, Wq, Wk, Wv, Wo);

    gemm_qkv_kernel<<<dim3(DD / 128, MM / 128, 3), 256, SMEM_GEMM>>>(bq, bk, bv);

    attn_tc_kernel<<<dim3(SS / 64, BB * HH), 128, ATT_SMEM>>>();

    gemm_o_kernel<<<dim3(DD / 128, MM / 128), 256, SMEM_GEMM>>>(bo, out);
}